// round 1
// baseline (speedup 1.0000x reference)
#include <cuda_runtime.h>
#include <cstdint>
#include <math.h>

#define BATCH 4
#define SEQ   4096
#define DIM   512
#define ROWS  (BATCH*SEQ)   // 16384
#define NCHUNK 32
#define CHUNK  128          // SEQ / NCHUNK
#define CLSZ   8            // cluster size for chain

// ---- scratch (no cudaMalloc allowed) ----
__device__ float g_R[ROWS*DIM];     // retention state r_t, row = b*SEQ+t
__device__ float g_G[ROWS*DIM];     // gates
__device__ float g_C[ROWS*DIM];     // r @ Bm^T
__device__ float g_S[ROWS*DIM];     // recurrent outputs s_t
__device__ float g_cf[BATCH*NCHUNK*DIM];  // chunk-final r
__device__ float g_cp[BATCH*NCHUNK*DIM];  // chunk-prefix r

// ============================================================
// Pass A / C: chunk-local scan. store=0: only chunk finals.
// store=1: init from g_cp, write full R.
// ============================================================
__global__ void scan_local(const float* __restrict__ k, const float* __restrict__ v,
                           const float* __restrict__ decay, int store)
{
    int g = blockIdx.x*blockDim.x + threadIdx.x;   // [0, BATCH*NCHUNK*DIM)
    int d = g % DIM;
    int c = (g / DIM) % NCHUNK;
    int b = g / (DIM*NCHUNK);
    float dec = decay[d >> 6];
    float r = store ? g_cp[g] : 0.0f;
    size_t base = ((size_t)b*SEQ + (size_t)c*CHUNK)*DIM + d;
    #pragma unroll 4
    for (int u = 0; u < CHUNK; u++) {
        size_t off = base + (size_t)u*DIM;
        r = fmaf(dec, r, k[off]*v[off]);
        if (store) g_R[off] = r;
    }
    if (!store) g_cf[g] = r;
}

// Pass B: combine chunk finals into chunk prefixes (per b,d lane)
__global__ void scan_prefix(const float* __restrict__ decay)
{
    int g = blockIdx.x*blockDim.x + threadIdx.x;   // [0, BATCH*DIM)
    int d = g % DIM;
    int b = g / DIM;
    float dec = decay[d >> 6];
    float dp = powf(dec, (float)CHUNK);
    float p = 0.0f;
    for (int c = 0; c < NCHUNK; c++) {
        int idx = (b*NCHUNK + c)*DIM + d;
        g_cp[idx] = p;
        p = g_cf[idx] + dp*p;
    }
}

// ============================================================
// GEMM: Y[M,512] = act(X[M,512] @ W[512,512]^T + bias)
// 128x128 tile, BK=16, 256 threads, 8x8 microtile, fp32
// act: 0 = none, 1 = sigmoid
// ============================================================
__global__ __launch_bounds__(256)
void gemm_kernel(const float* __restrict__ X, const float* __restrict__ W,
                 const float* __restrict__ bias, float* __restrict__ Y, int act)
{
    __shared__ float Xs[16][132];
    __shared__ float Ws[16][132];
    const int K = DIM;
    int tid  = threadIdx.x;
    int m0   = blockIdx.y * 128;
    int n0   = blockIdx.x * 128;
    int rowc = (tid >> 4) << 3;   // 0..120
    int colc = (tid & 15) << 3;   // 0..120

    float acc[8][8];
    #pragma unroll
    for (int i = 0; i < 8; i++)
        #pragma unroll
        for (int j = 0; j < 8; j++) acc[i][j] = 0.0f;

    for (int kt = 0; kt < K; kt += 16) {
        #pragma unroll
        for (int l = 0; l < 2; l++) {
            int idx = tid + l*256;        // 0..511
            int row = idx >> 2;           // 0..127
            int fc  = (idx & 3) << 2;     // 0,4,8,12
            float4 xv = *(const float4*)(X + (size_t)(m0+row)*K + kt + fc);
            Xs[fc+0][row]=xv.x; Xs[fc+1][row]=xv.y; Xs[fc+2][row]=xv.z; Xs[fc+3][row]=xv.w;
            float4 wv = *(const float4*)(W + (size_t)(n0+row)*K + kt + fc);
            Ws[fc+0][row]=wv.x; Ws[fc+1][row]=wv.y; Ws[fc+2][row]=wv.z; Ws[fc+3][row]=wv.w;
        }
        __syncthreads();
        #pragma unroll
        for (int kk = 0; kk < 16; kk++) {
            float ar[8], br[8];
            *(float4*)(ar  ) = *(const float4*)&Xs[kk][rowc];
            *(float4*)(ar+4) = *(const float4*)&Xs[kk][rowc+4];
            *(float4*)(br  ) = *(const float4*)&Ws[kk][colc];
            *(float4*)(br+4) = *(const float4*)&Ws[kk][colc+4];
            #pragma unroll
            for (int i = 0; i < 8; i++)
                #pragma unroll
                for (int j = 0; j < 8; j++)
                    acc[i][j] = fmaf(ar[i], br[j], acc[i][j]);
        }
        __syncthreads();
    }

    #pragma unroll
    for (int i = 0; i < 8; i++) {
        #pragma unroll
        for (int j = 0; j < 8; j++) {
            float val = acc[i][j] + (bias ? bias[n0+colc+j] : 0.0f);
            if (act == 1) val = 1.0f/(1.0f + expf(-val));
            Y[(size_t)(m0+rowc+i)*DIM + n0+colc+j] = val;
        }
    }
}

// ============================================================
// Sequential chain: 4 batches x 8-CTA clusters.
// Each CTA: 512 threads, owns 64 output rows of A (in registers).
// blended (512-wide) all-gathered per step via DSMEM + cluster.sync.
// ============================================================
__device__ __forceinline__ uint32_t smem_u32(const void* p) {
    return (uint32_t)__cvta_generic_to_shared(p);
}
__device__ __forceinline__ void cluster_store_f32(float* p, int rank, float v) {
    uint32_t a = smem_u32(p);
    uint32_t ra;
    asm volatile("mapa.shared::cluster.u32 %0, %1, %2;" : "=r"(ra) : "r"(a), "r"(rank));
    asm volatile("st.shared::cluster.f32 [%0], %1;" :: "r"(ra), "f"(v) : "memory");
}
#define CLUSTER_SYNC() do { \
    asm volatile("barrier.cluster.arrive.aligned;" ::: "memory"); \
    asm volatile("barrier.cluster.wait.aligned;"   ::: "memory"); } while (0)

__global__ void __launch_bounds__(512, 1) __cluster_dims__(CLSZ, 1, 1)
chain_kernel(const float* __restrict__ q, const float* __restrict__ A,
             const float* __restrict__ G, const float* __restrict__ C,
             float* __restrict__ Sout)
{
    __shared__ float bl[2][DIM];   // double-buffered blended vector
    __shared__ float ybuf[64];

    int rank = blockIdx.x & (CLSZ-1);
    int b    = blockIdx.x / CLSZ;
    int tid  = threadIdx.x;
    int jl   = tid >> 3;           // 0..63 output row within slice
    int part = tid & 7;            // 0..7  k-partition
    int jg   = rank*64 + jl;       // global output row (0..511)

    // A rows for this thread, interleaved so blended LDS128 reads are conflict-free:
    // thread covers i = 4*(part + 8u) + c,  u=0..15, c=0..3
    float4 areg[16];
    #pragma unroll
    for (int u = 0; u < 16; u++)
        areg[u] = *(const float4*)(A + (size_t)jg*DIM + 4*(part + 8*u));

    const float* qb = q + (size_t)b*SEQ*DIM;
    const float* Gb = G + (size_t)b*SEQ*DIM;
    const float* Cb = C + (size_t)b*SEQ*DIM;
    float*       Sb = Sout + (size_t)b*SEQ*DIM;

    float cc = 0.f, cg = 0.f, cq = 0.f;   // c_t, g_{t+1}, q_{t+1}
    if (tid < 64) {
        int j = rank*64 + tid;
        float g0 = Gb[j], q0 = qb[j];
        float bv = (1.0f - g0) * q0;      // state_0 = 0
        #pragma unroll
        for (int r = 0; r < CLSZ; r++) cluster_store_f32(&bl[0][j], r, bv);
        cc = Cb[j];
        cg = Gb[DIM + j];
        cq = qb[DIM + j];
    }
    CLUSTER_SYNC();

    for (int t = 0; t < SEQ; t++) {
        int p = t & 1;
        // prefetch next step's operands (hidden under MAC phase)
        float nc = 0.f, ng = 0.f, nq = 0.f;
        if (tid < 64) {
            int j = rank*64 + tid;
            if (t+1 < SEQ) nc = Cb[(size_t)(t+1)*DIM + j];
            if (t+2 < SEQ) { ng = Gb[(size_t)(t+2)*DIM + j]; nq = qb[(size_t)(t+2)*DIM + j]; }
        }
        // partial dot: 64 MACs/thread
        float a0=0.f, a1=0.f, a2=0.f, a3=0.f;
        #pragma unroll
        for (int u = 0; u < 16; u++) {
            float4 bv = *(const float4*)&bl[p][4*(part + 8*u)];
            a0 = fmaf(areg[u].x, bv.x, a0);
            a1 = fmaf(areg[u].y, bv.y, a1);
            a2 = fmaf(areg[u].z, bv.z, a2);
            a3 = fmaf(areg[u].w, bv.w, a3);
        }
        float acc = (a0+a1) + (a2+a3);
        // reduce across 8 parts (contiguous lanes)
        acc += __shfl_xor_sync(0xffffffffu, acc, 1);
        acc += __shfl_xor_sync(0xffffffffu, acc, 2);
        acc += __shfl_xor_sync(0xffffffffu, acc, 4);
        if (part == 0) ybuf[jl] = acc;
        __syncthreads();

        if (tid < 64) {
            int j = rank*64 + tid;
            float s = tanhf(ybuf[tid] + cc);
            Sb[(size_t)t*DIM + j] = s;
            if (t+1 < SEQ) {
                float bv = fmaf(cg, s - cq, cq);   // cg*s + (1-cg)*cq
                #pragma unroll
                for (int r = 0; r < CLSZ; r++) cluster_store_f32(&bl[1-p][j], r, bv);
            }
        }
        cc = nc; cg = ng; cq = nq;
        CLUSTER_SYNC();   // publish bl[1-p] to whole cluster, also CTA barrier
    }
}

// ============================================================
// launch
// ============================================================
extern "C" void kernel_launch(void* const* d_in, const int* in_sizes, int n_in,
                              void* d_out, int out_size)
{
    const float* q     = (const float*)d_in[0];
    const float* k     = (const float*)d_in[1];
    const float* v     = (const float*)d_in[2];
    const float* A     = (const float*)d_in[3];
    const float* Bm    = (const float*)d_in[4];
    const float* gw    = (const float*)d_in[5];
    const float* gb    = (const float*)d_in[6];
    const float* ow    = (const float*)d_in[7];
    const float* ob    = (const float*)d_in[8];
    const float* decay = (const float*)d_in[9];
    float* out = (float*)d_out;

    float *R, *G, *C, *S;
    cudaGetSymbolAddress((void**)&R, g_R);
    cudaGetSymbolAddress((void**)&G, g_G);
    cudaGetSymbolAddress((void**)&C, g_C);
    cudaGetSymbolAddress((void**)&S, g_S);

    // 1) chunked linear scan for r
    scan_local <<<BATCH*NCHUNK*DIM/256, 256>>>(k, v, decay, 0);
    scan_prefix<<<BATCH*DIM/256,        256>>>(decay);
    scan_local <<<BATCH*NCHUNK*DIM/256, 256>>>(k, v, decay, 1);

    dim3 ggrid(DIM/128, ROWS/128);   // (4, 128)
    // 2) gates (sigmoid epilogue)
    gemm_kernel<<<ggrid, 256>>>(q, gw, gb, G, 1);
    // 3) C = R @ Bm^T
    gemm_kernel<<<ggrid, 256>>>(R, Bm, nullptr, C, 0);
    // 4) sequential recurrent chain (4 clusters of 8 CTAs)
    chain_kernel<<<BATCH*CLSZ, 512>>>(q, A, G, C, S);
    // 5) out projection
    gemm_kernel<<<ggrid, 256>>>(S, ow, ob, out, 0);
}

// round 2
// speedup vs baseline: 1.1822x; 1.1822x over previous
#include <cuda_runtime.h>
#include <cstdint>
#include <math.h>

#define BATCH 4
#define SEQ   4096
#define DIM   512
#define ROWS  (BATCH*SEQ)   // 16384
#define NCHUNK 32
#define CHUNK  128          // SEQ / NCHUNK
#define CLSZ   8            // cluster size for chain

// ---- scratch (no cudaMalloc allowed) ----
__device__ float g_R[ROWS*DIM];     // retention state r_t
__device__ float g_G[ROWS*DIM];     // gates
__device__ float g_C[ROWS*DIM];     // r @ Bm^T
__device__ float g_S[ROWS*DIM];     // recurrent outputs s_t
__device__ float g_cf[BATCH*NCHUNK*DIM];
__device__ float g_cp[BATCH*NCHUNK*DIM];

// ---------------- helpers ----------------
__device__ __forceinline__ uint32_t smem_u32(const void* p) {
    return (uint32_t)__cvta_generic_to_shared(p);
}
__device__ __forceinline__ void fma2(unsigned long long& d, unsigned long long a, unsigned long long b) {
    asm("fma.rn.f32x2 %0, %1, %2, %0;" : "+l"(d) : "l"(a), "l"(b));
}
__device__ __forceinline__ unsigned long long dupf(float a) {
    unsigned long long r;
    asm("mov.b64 %0, {%1, %1};" : "=l"(r) : "f"(a));
    return r;
}
__device__ __forceinline__ void unpack2(unsigned long long v, float& lo, float& hi) {
    asm("mov.b64 {%0, %1}, %2;" : "=f"(lo), "=f"(hi) : "l"(v));
}
__device__ __forceinline__ void mbar_init(uint32_t addr, uint32_t cnt) {
    asm volatile("mbarrier.init.shared.b64 [%0], %1;" :: "r"(addr), "r"(cnt) : "memory");
}
__device__ __forceinline__ void mbar_expect_tx(uint32_t addr, uint32_t bytes) {
    asm volatile("mbarrier.arrive.expect_tx.shared.b64 _, [%0], %1;" :: "r"(addr), "r"(bytes) : "memory");
}
__device__ __forceinline__ void st_async_u32(uint32_t raddr, uint32_t val, uint32_t rmbar) {
    asm volatile("st.async.weak.shared::cluster.mbarrier::complete_tx::bytes.b32 [%0], %1, [%2];"
                 :: "r"(raddr), "r"(val), "r"(rmbar) : "memory");
}
__device__ __forceinline__ void mbar_wait_cluster(uint32_t addr, uint32_t parity) {
    uint32_t done;
    asm volatile("{\n\t.reg .pred P;\n\t"
        "mbarrier.try_wait.parity.acquire.cluster.shared::cta.b64 P, [%1], %2, 0x989680;\n\t"
        "selp.b32 %0, 1, 0, P;\n\t}"
        : "=r"(done) : "r"(addr), "r"(parity) : "memory");
    while (!done) {
        asm volatile("{\n\t.reg .pred P;\n\t"
            "mbarrier.try_wait.parity.acquire.cluster.shared::cta.b64 P, [%1], %2, 0x989680;\n\t"
            "selp.b32 %0, 1, 0, P;\n\t}"
            : "=r"(done) : "r"(addr), "r"(parity) : "memory");
    }
}
#define CLUSTER_SYNC() do { \
    asm volatile("barrier.cluster.arrive.aligned;" ::: "memory"); \
    asm volatile("barrier.cluster.wait.aligned;"   ::: "memory"); } while (0)

// ============================================================
// Chunked linear scan for r
// ============================================================
__global__ void scan_local(const float* __restrict__ k, const float* __restrict__ v,
                           const float* __restrict__ decay, int store)
{
    int g = blockIdx.x*blockDim.x + threadIdx.x;
    int d = g % DIM;
    int c = (g / DIM) % NCHUNK;
    int b = g / (DIM*NCHUNK);
    float dec = decay[d >> 6];
    float r = store ? g_cp[g] : 0.0f;
    size_t base = ((size_t)b*SEQ + (size_t)c*CHUNK)*DIM + d;
    #pragma unroll 4
    for (int u = 0; u < CHUNK; u++) {
        size_t off = base + (size_t)u*DIM;
        r = fmaf(dec, r, k[off]*v[off]);
        if (store) g_R[off] = r;
    }
    if (!store) g_cf[g] = r;
}

__global__ void scan_prefix(const float* __restrict__ decay)
{
    int g = blockIdx.x*blockDim.x + threadIdx.x;
    int d = g % DIM;
    int b = g / DIM;
    float dec = decay[d >> 6];
    float dp = powf(dec, (float)CHUNK);
    float p = 0.0f;
    for (int c = 0; c < NCHUNK; c++) {
        int idx = (b*NCHUNK + c)*DIM + d;
        g_cp[idx] = p;
        p = g_cf[idx] + dp*p;
    }
}

// ============================================================
// GEMM: Y[M,512] = act(X[M,512] @ W[512,512]^T + bias), f32x2 inner
// ============================================================
__global__ __launch_bounds__(256)
void gemm_kernel(const float* __restrict__ X, const float* __restrict__ W,
                 const float* __restrict__ bias, float* __restrict__ Y, int act)
{
    __shared__ __align__(16) float Xs[16][132];
    __shared__ __align__(16) float Ws[16][132];
    const int K = DIM;
    int tid  = threadIdx.x;
    int m0   = blockIdx.y * 128;
    int n0   = blockIdx.x * 128;
    int rowc = (tid >> 4) << 3;
    int colc = (tid & 15) << 3;

    unsigned long long acc2[8][4];
    #pragma unroll
    for (int i = 0; i < 8; i++)
        #pragma unroll
        for (int j = 0; j < 4; j++) acc2[i][j] = 0ull;

    for (int kt = 0; kt < K; kt += 16) {
        #pragma unroll
        for (int l = 0; l < 2; l++) {
            int idx = tid + l*256;
            int row = idx >> 2;
            int fc  = (idx & 3) << 2;
            float4 xv = *(const float4*)(X + (size_t)(m0+row)*K + kt + fc);
            Xs[fc+0][row]=xv.x; Xs[fc+1][row]=xv.y; Xs[fc+2][row]=xv.z; Xs[fc+3][row]=xv.w;
            float4 wv = *(const float4*)(W + (size_t)(n0+row)*K + kt + fc);
            Ws[fc+0][row]=wv.x; Ws[fc+1][row]=wv.y; Ws[fc+2][row]=wv.z; Ws[fc+3][row]=wv.w;
        }
        __syncthreads();
        #pragma unroll
        for (int kk = 0; kk < 16; kk++) {
            float ar[8];
            *(float4*)(ar  ) = *(const float4*)&Xs[kk][rowc];
            *(float4*)(ar+4) = *(const float4*)&Xs[kk][rowc+4];
            ulonglong2 blo = *(const ulonglong2*)&Ws[kk][colc];
            ulonglong2 bhi = *(const ulonglong2*)&Ws[kk][colc+4];
            #pragma unroll
            for (int i = 0; i < 8; i++) {
                unsigned long long ad = dupf(ar[i]);
                fma2(acc2[i][0], ad, blo.x);
                fma2(acc2[i][1], ad, blo.y);
                fma2(acc2[i][2], ad, bhi.x);
                fma2(acc2[i][3], ad, bhi.y);
            }
        }
        __syncthreads();
    }

    #pragma unroll
    for (int i = 0; i < 8; i++) {
        float out[8];
        #pragma unroll
        for (int jp = 0; jp < 4; jp++) unpack2(acc2[i][jp], out[2*jp], out[2*jp+1]);
        #pragma unroll
        for (int j = 0; j < 8; j++) {
            float val = out[j] + (bias ? bias[n0+colc+j] : 0.0f);
            if (act == 1) val = 1.0f/(1.0f + expf(-val));
            Y[(size_t)(m0+rowc+i)*DIM + n0+colc+j] = val;
        }
    }
}

// ============================================================
// Sequential chain: 4 batches x 8-CTA clusters, mbarrier all-gather,
// f32x2 MACs, distributed epilogue.
// ============================================================
__global__ void __launch_bounds__(512, 1) __cluster_dims__(CLSZ, 1, 1)
chain_kernel(const float* __restrict__ q, const float* __restrict__ A,
             const float* __restrict__ G, const float* __restrict__ C,
             float* __restrict__ Sout)
{
    __shared__ __align__(16) float bl[2][DIM];           // double-buffered blended
    __shared__ __align__(8)  unsigned long long mbar[2]; // full-barriers per buffer

    int rank = blockIdx.x & (CLSZ-1);
    int b    = blockIdx.x / CLSZ;
    int tid  = threadIdx.x;
    int jl   = tid >> 3;       // 0..63 output row within slice
    int part = tid & 7;        // 0..7  k-partition
    int jg   = rank*64 + jl;   // global output row
    bool wr  = (part == 0);    // epilogue/writer lane

    uint32_t bl_a = smem_u32(&bl[0][0]);
    uint32_t mb_a = smem_u32(&mbar[0]);
    uint32_t dmb  = mb_a - bl_a;

    if (tid == 0) { mbar_init(mb_a, 1); mbar_init(mb_a + 8, 1); }

    // remote SMEM base (bl[0][0]) of every cluster CTA
    uint32_t rb[CLSZ];
    #pragma unroll
    for (int r = 0; r < CLSZ; r++)
        asm("mapa.shared::cluster.u32 %0, %1, %2;" : "=r"(rb[r]) : "r"(bl_a), "r"(r));

    // A rows in registers as f32x2 pairs; thread covers k = 4*(part+8u)+{0..3}
    unsigned long long a2[32];
    #pragma unroll
    for (int u = 0; u < 16; u++) {
        ulonglong2 av = *(const ulonglong2*)(A + (size_t)jg*DIM + 4*(part + 8*u));
        a2[2*u] = av.x; a2[2*u+1] = av.y;
    }

    const float* qb = q    + (size_t)b*SEQ*DIM;
    const float* Gb = G    + (size_t)b*SEQ*DIM;
    const float* Cb = C    + (size_t)b*SEQ*DIM;
    float*       Sb = Sout + (size_t)b*SEQ*DIM;

    CLUSTER_SYNC();   // barriers initialized cluster-wide before any st.async

    float cc = 0.f, cg = 0.f, cq = 0.f;
    if (tid == 0) mbar_expect_tx(mb_a, 2048);
    if (wr) {
        float g0 = Gb[jg], q0 = qb[jg];
        uint32_t bits = __float_as_uint((1.0f - g0) * q0);   // state_0 = 0
        #pragma unroll
        for (int r = 0; r < CLSZ; r++)
            st_async_u32(rb[r] + jg*4u, bits, rb[r] + dmb);
        cc = Cb[jg]; cg = Gb[DIM + jg]; cq = qb[DIM + jg];
    }

    for (int t = 0; t < SEQ; t++) {
        int p = t & 1;
        uint32_t ph = (t >> 1) & 1;

        // prefetch next operands + arm next barrier BEFORE waiting
        float nc = 0.f, ng = 0.f, nq = 0.f;
        if (wr) {
            if (t+1 < SEQ) nc = Cb[(size_t)(t+1)*DIM + jg];
            if (t+2 < SEQ) { ng = Gb[(size_t)(t+2)*DIM + jg]; nq = qb[(size_t)(t+2)*DIM + jg]; }
        }
        if (tid == 0 && t+1 < SEQ) mbar_expect_tx(mb_a + (uint32_t)(1-p)*8u, 2048);

        mbar_wait_cluster(mb_a + (uint32_t)p*8u, ph);

        // partial dot: 64 MACs/thread as 32 f32x2 FMAs
        unsigned long long acc0 = 0ull, acc1 = 0ull;
        const float* blp = bl[p];
        #pragma unroll
        for (int u = 0; u < 16; u++) {
            ulonglong2 bv = *(const ulonglong2*)(blp + 4*(part + 8*u));
            fma2(acc0, a2[2*u],   bv.x);
            fma2(acc1, a2[2*u+1], bv.y);
        }
        float x0, x1, y0, y1;
        unpack2(acc0, x0, x1);
        unpack2(acc1, y0, y1);
        float acc = (x0 + x1) + (y0 + y1);
        acc += __shfl_xor_sync(0xffffffffu, acc, 1);
        acc += __shfl_xor_sync(0xffffffffu, acc, 2);
        acc += __shfl_xor_sync(0xffffffffu, acc, 4);

        // all warps done reading bl[p]; (combined with the barrier-gating of
        // step t+1 by our st.async below, this makes buffer reuse race-free)
        __syncthreads();

        if (wr) {
            float s = tanhf(acc + cc);
            Sb[(size_t)t*DIM + jg] = s;
            if (t+1 < SEQ) {
                uint32_t bits = __float_as_uint(fmaf(cg, s - cq, cq)); // g*s+(1-g)*q
                uint32_t boff = (uint32_t)(1-p)*2048u + (uint32_t)jg*4u;
                uint32_t moff = dmb + (uint32_t)(1-p)*8u;
                #pragma unroll
                for (int r = 0; r < CLSZ; r++)
                    st_async_u32(rb[r] + boff, bits, rb[r] + moff);
            }
            cc = nc; cg = ng; cq = nq;
        }
    }
}

// ============================================================
// launch
// ============================================================
extern "C" void kernel_launch(void* const* d_in, const int* in_sizes, int n_in,
                              void* d_out, int out_size)
{
    const float* q     = (const float*)d_in[0];
    const float* k     = (const float*)d_in[1];
    const float* v     = (const float*)d_in[2];
    const float* A     = (const float*)d_in[3];
    const float* Bm    = (const float*)d_in[4];
    const float* gw    = (const float*)d_in[5];
    const float* gb    = (const float*)d_in[6];
    const float* ow    = (const float*)d_in[7];
    const float* ob    = (const float*)d_in[8];
    const float* decay = (const float*)d_in[9];
    float* out = (float*)d_out;

    float *R, *G, *C, *S;
    cudaGetSymbolAddress((void**)&R, g_R);
    cudaGetSymbolAddress((void**)&G, g_G);
    cudaGetSymbolAddress((void**)&C, g_C);
    cudaGetSymbolAddress((void**)&S, g_S);

    // 1) chunked linear scan for r
    scan_local <<<BATCH*NCHUNK*DIM/256, 256>>>(k, v, decay, 0);
    scan_prefix<<<BATCH*DIM/256,        256>>>(decay);
    scan_local <<<BATCH*NCHUNK*DIM/256, 256>>>(k, v, decay, 1);

    dim3 ggrid(DIM/128, ROWS/128);
    // 2) gates (sigmoid epilogue)
    gemm_kernel<<<ggrid, 256>>>(q, gw, gb, G, 1);
    // 3) C = R @ Bm^T
    gemm_kernel<<<ggrid, 256>>>(R, Bm, nullptr, C, 0);
    // 4) sequential recurrent chain (4 clusters of 8 CTAs)
    chain_kernel<<<BATCH*CLSZ, 512>>>(q, A, G, C, S);
    // 5) out projection
    gemm_kernel<<<ggrid, 256>>>(S, ow, ob, out, 0);
}